// round 9
// baseline (speedup 1.0000x reference)
#include <cuda_runtime.h>
#include <math.h>

// ---------------- problem constants ----------------
constexpr int kN  = 10000;
constexpr int kE  = 160000;
constexpr int kNG = 16;
constexpr int kT  = 5;
constexpr int kF  = 80;       // channels
constexpr int kFO = 16;       // out per tower
constexpr int kC  = kT * kF;  // 400 message channels
// AVG_DEG_LOG = log(17.0)
__device__ __constant__ float kAvgDegLog = 2.8332133440562162f;

// ---------------- scratch (static device globals: allowed) ----------------
__device__ __align__(16) float g_h   [kN * 80];
__device__ __align__(16) float g_hij [kN * 800];        // hi = [0,400), hj = [400,800)
__device__ __align__(16) float g_agg [kN * 1600];       // [n][t*320 + j*80 + f], j=mean,min,max,std
__device__ __align__(16) float g_t48 [kN * 240];        // [n][t*48 + (id|amp|att)*16 + g]
__device__ __align__(16) float g_tph [kN * 80];
__device__ __align__(16) float g_comb[kN * 80];
__device__ __align__(16) float g_y   [kN * 80];
__device__ __align__(16) float g_W1  [800 * 80];
__device__ __align__(16) float g_W2  [kT * 48 * 320];
__device__ float  g_amp[kN];
__device__ float  g_inv[kN];
__device__ float  g_pool[kNG * 80];
__device__ double g_bsum[80];
__device__ double g_bsq [80];
__device__ int g_deg[kN];
__device__ int g_off[kN + 1];
__device__ int g_cur[kN];
__device__ int g_ssrc[kE];

// ---------------- small utility kernels ----------------
__global__ void k_embed(const int* __restrict__ x, const float* __restrict__ emb,
                        float* __restrict__ h) {
    int idx = blockIdx.x * blockDim.x + threadIdx.x;   // over N*40
    if (idx >= kN * 40) return;
    int n = idx / 40, k = idx % 40;
    int tok = x[idx];
    h[n * 80 + 2 * k + 0] = emb[tok * 2 + 0];
    h[n * 80 + 2 * k + 1] = emb[tok * 2 + 1];
}

__global__ void k_zero_int(int* p, int n) {
    int i = blockIdx.x * blockDim.x + threadIdx.x;
    if (i < n) p[i] = 0;
}
__global__ void k_zero_float(float* p, int n) {
    int i = blockIdx.x * blockDim.x + threadIdx.x;
    if (i < n) p[i] = 0.0f;
}
__global__ void k_zero_bn(double* s, double* q) {
    int i = threadIdx.x;
    if (i < 80) { s[i] = 0.0; q[i] = 0.0; }
}

__global__ void k_count(const int* __restrict__ ei, int* __restrict__ deg) {
    int e = blockIdx.x * blockDim.x + threadIdx.x;
    if (e < kE) atomicAdd(&deg[ei[kE + e]], 1);
}

// single-block scan: deg -> exclusive offsets, zero cursors
__global__ void k_scan(const int* __restrict__ deg, int* __restrict__ off,
                       int* __restrict__ cur) {
    __shared__ int part[1024];
    const int CH = 10;  // 1024*10 >= kN
    int t = threadIdx.x;
    int base = t * CH;
    int local[CH];
    int s = 0;
#pragma unroll
    for (int i = 0; i < CH; i++) {
        int idx = base + i;
        int v = (idx < kN) ? deg[idx] : 0;
        local[i] = s;
        s += v;
    }
    part[t] = s;
    __syncthreads();
    for (int d = 1; d < 1024; d <<= 1) {
        int v = (t >= d) ? part[t - d] : 0;
        __syncthreads();
        part[t] += v;
        __syncthreads();
    }
    int pre = (t > 0) ? part[t - 1] : 0;
#pragma unroll
    for (int i = 0; i < CH; i++) {
        int idx = base + i;
        if (idx < kN) { off[idx] = pre + local[i]; cur[idx] = 0; }
    }
    if (t == 1023) off[kN] = part[1023];
}

__global__ void k_scatter(const int* __restrict__ ei, const int* __restrict__ off,
                          int* __restrict__ cur, int* __restrict__ ssrc) {
    int e = blockIdx.x * blockDim.x + threadIdx.x;
    if (e >= kE) return;
    int d = ei[kE + e];
    int p = atomicAdd(&cur[d], 1);
    ssrc[off[d] + p] = ei[e];
}

// repack pre_w (T,F,2F) -> W1[800][80]: rows 0..399 target half, 400..799 source half
__global__ void k_repack1(const float* __restrict__ pw, float* __restrict__ W1) {
    int idx = blockIdx.x * blockDim.x + threadIdx.x;   // 800*80
    if (idx >= 800 * 80) return;
    int o = idx / 80, k = idx % 80;
    W1[idx] = (o < 400) ? pw[o * 160 + k] : pw[(o - 400) * 160 + 80 + k];
}

// repack post_w (T,16,1040) agg slices -> W2[t][48][320] (48 = id16|amp16|att16)
__global__ void k_repack2(const float* __restrict__ ow, float* __restrict__ W2) {
    int idx = blockIdx.x * blockDim.x + threadIdx.x;   // 5*48*320
    if (idx >= kT * 48 * 320) return;
    int t = idx / (48 * 320);
    int r = idx % (48 * 320);
    int j = r / 320, k = r % 320;
    int s = j / 16, g = j % 16;
    W2[idx] = ow[t * 16 * 1040 + g * 1040 + 80 + s * 320 + k];
}

// ---------------- generic fp32 GEMM: C[m,n] = sum_k A[m,k]*B[n,k] (+bias[n]) -------
// BM=64 BN=64 BK=16, 256 threads, 4x4 micro-tiles. Requires K%16==0, ld%4==0, 16B-aligned bases.
__global__ void k_gemm(const float* __restrict__ A, int lda, long long aStr,
                       const float* __restrict__ B, int ldb, long long bStr,
                       float* __restrict__ C, int ldc, long long cStr,
                       const float* __restrict__ bias,
                       int M, int Nn, int K) {
    int bz = blockIdx.z;
    A += (size_t)bz * aStr;
    B += (size_t)bz * bStr;
    C += (size_t)bz * cStr;

    __shared__ float As[16][64];
    __shared__ float Bs[16][64];

    int tid = threadIdx.x;
    int m0 = blockIdx.x * 64, n0 = blockIdx.y * 64;
    int tm = (tid / 16) * 4;
    int tn = (tid % 16) * 4;
    int lr = tid / 4;           // 0..63
    int lc = (tid % 4) * 4;     // 0,4,8,12

    float acc[4][4] = {{0,0,0,0},{0,0,0,0},{0,0,0,0},{0,0,0,0}};

    for (int k0 = 0; k0 < K; k0 += 16) {
        float4 va = make_float4(0.f, 0.f, 0.f, 0.f);
        int m = m0 + lr;
        if (m < M) va = *(const float4*)(A + (size_t)m * lda + k0 + lc);
        As[lc + 0][lr] = va.x; As[lc + 1][lr] = va.y;
        As[lc + 2][lr] = va.z; As[lc + 3][lr] = va.w;

        float4 vb = make_float4(0.f, 0.f, 0.f, 0.f);
        int nn = n0 + lr;
        if (nn < Nn) vb = *(const float4*)(B + (size_t)nn * ldb + k0 + lc);
        Bs[lc + 0][lr] = vb.x; Bs[lc + 1][lr] = vb.y;
        Bs[lc + 2][lr] = vb.z; Bs[lc + 3][lr] = vb.w;

        __syncthreads();
#pragma unroll
        for (int k = 0; k < 16; k++) {
            float4 a = *(const float4*)&As[k][tm];
            float4 b = *(const float4*)&Bs[k][tn];
            acc[0][0] += a.x * b.x; acc[0][1] += a.x * b.y; acc[0][2] += a.x * b.z; acc[0][3] += a.x * b.w;
            acc[1][0] += a.y * b.x; acc[1][1] += a.y * b.y; acc[1][2] += a.y * b.z; acc[1][3] += a.y * b.w;
            acc[2][0] += a.z * b.x; acc[2][1] += a.z * b.y; acc[2][2] += a.z * b.z; acc[2][3] += a.z * b.w;
            acc[3][0] += a.w * b.x; acc[3][1] += a.w * b.y; acc[3][2] += a.w * b.z; acc[3][3] += a.w * b.w;
        }
        __syncthreads();
    }

#pragma unroll
    for (int i = 0; i < 4; i++) {
        int m = m0 + tm + i;
        if (m >= M) continue;
#pragma unroll
        for (int j = 0; j < 4; j++) {
            int nn = n0 + tn + j;
            if (nn < Nn) {
                float v = acc[i][j];
                if (bias) v += bias[nn];
                C[(size_t)m * ldc + nn] = v;
            }
        }
    }
}

// ---------------- per-node aggregation (CSR) ----------------
// one block per node, 128 threads, 4 channels/thread (400 channels)
__global__ void k_aggregate(const float* __restrict__ hij, const float* __restrict__ pre_b,
                            const int* __restrict__ off, const int* __restrict__ ssrc,
                            float* __restrict__ agg, float* __restrict__ amp,
                            float* __restrict__ inva) {
    int n = blockIdx.x;
    int tid = threadIdx.x;
    int t0 = off[n], t1 = off[n + 1];
    int deg = t1 - t0;

    const float BIG = 3.4e38f;
    float base[4], sm[4], s2[4], mn[4], mx[4];
#pragma unroll
    for (int j = 0; j < 4; j++) {
        int c = tid + j * 128;
        base[j] = (c < kC) ? (hij[(size_t)n * 800 + c] + pre_b[c]) : 0.0f;
        sm[j] = 0.f; s2[j] = 0.f; mn[j] = BIG; mx[j] = -BIG;
    }

    __shared__ int sh[64];
    for (int b = t0; b < t1; b += 64) {
        int cnt = min(64, t1 - b);
        __syncthreads();
        if (tid < cnt) sh[tid] = ssrc[b + tid];
        __syncthreads();
        for (int kk = 0; kk < cnt; kk++) {
            int s = sh[kk];
            const float* row = hij + (size_t)s * 800 + 400;
#pragma unroll
            for (int j = 0; j < 4; j++) {
                int c = tid + j * 128;
                if (c < kC) {
                    float v = base[j] + row[c];
                    sm[j] += v;
                    s2[j] += v * v;
                    mn[j] = fminf(mn[j], v);
                    mx[j] = fmaxf(mx[j], v);
                }
            }
        }
    }

    float degc = (float)max(deg, 1);
    float rd = 1.0f / degc;
#pragma unroll
    for (int j = 0; j < 4; j++) {
        int c = tid + j * 128;
        if (c < kC) {
            float mean  = sm[j] * rd;
            float mean2 = s2[j] * rd;
            float var   = fmaxf(mean2 - mean * mean, 0.0f);
            float stdv  = sqrtf(var + 1e-5f);
            float vmn = (deg > 0) ? mn[j] : 0.0f;
            float vmx = (deg > 0) ? mx[j] : 0.0f;
            int t = c / 80, f = c % 80;
            size_t b = (size_t)n * 1600 + (size_t)t * 320 + f;
            agg[b + 0]   = mean;
            agg[b + 80]  = vmn;
            agg[b + 160] = vmx;
            agg[b + 240] = stdv;
        }
    }
    if (tid == 0) {
        float a = logf(degc + 1.0f) / kAvgDegLog;
        amp[n]  = a;
        inva[n] = 1.0f / a;
    }
}

// combine: out80 = h-part + id + amp*amp_part + inv*att_part + post_b
__global__ void k_combine(const float* __restrict__ tph, const float* __restrict__ t48,
                          const float* __restrict__ amp, const float* __restrict__ inva,
                          const float* __restrict__ pb, float* __restrict__ comb) {
    int idx = blockIdx.x * blockDim.x + threadIdx.x;   // N*80
    if (idx >= kN * 80) return;
    int n = idx / 80, tg = idx % 80;
    int t = tg / 16, g = tg % 16;
    size_t b = (size_t)n * 240 + t * 48;
    comb[idx] = tph[idx] + t48[b + g] + amp[n] * t48[b + 16 + g]
              + inva[n] * t48[b + 32 + g] + pb[tg];
}

// batchnorm stats: double accumulation
__global__ void k_bnstats(const float* __restrict__ y, double* __restrict__ bs,
                          double* __restrict__ bq) {
    __shared__ double s1[240], s2[240];
    int t = threadIdx.x;
    if (t < 240) {
        int c = t % 80;
        int rl = blockIdx.x * 3 + t / 80;
        int stride = gridDim.x * 3;
        double a = 0.0, b = 0.0;
        for (int r = rl; r < kN; r += stride) {
            float v = y[(size_t)r * 80 + c];
            a += (double)v;
            b += (double)v * (double)v;
        }
        s1[t] = a; s2[t] = b;
    }
    __syncthreads();
    if (t < 80) {
        atomicAdd(&bs[t], s1[t] + s1[t + 80] + s1[t + 160]);
        atomicAdd(&bq[t], s2[t] + s2[t + 80] + s2[t + 160]);
    }
}

__global__ void k_bnapply(const float* __restrict__ y, const double* __restrict__ bs,
                          const double* __restrict__ bq, const float* __restrict__ gam,
                          const float* __restrict__ bet, float* __restrict__ h) {
    int idx = blockIdx.x * blockDim.x + threadIdx.x;   // N*80
    if (idx >= kN * 80) return;
    int c = idx % 80;
    double mu  = bs[c] / (double)kN;
    double var = bq[c] / (double)kN - mu * mu;
    if (var < 0.0) var = 0.0;
    float sc = (float)(1.0 / sqrt(var + 1e-5));
    float v = (y[idx] - (float)mu) * sc * gam[c] + bet[c];
    h[idx] = fmaxf(v, 0.0f);
}

// max-pool per graph (values >= 0 after relu -> int-compare valid, init 0 matches ref)
__global__ void k_pool(const float* __restrict__ h, const int* __restrict__ bat,
                       float* __restrict__ pool) {
    int idx = blockIdx.x * blockDim.x + threadIdx.x;   // N*80
    if (idx >= kN * 80) return;
    int n = idx / 80, c = idx % 80;
    int g = bat[n];
    atomicMax((int*)&pool[g * 80 + c], __float_as_int(h[idx]));
}

__global__ void k_fc(const float* __restrict__ pool, const float* __restrict__ fw,
                     const float* __restrict__ fb, float* __restrict__ out) {
    int t = threadIdx.x;   // 320 = 16*20
    if (t >= kNG * 20) return;
    int g = t / 20, o = t % 20;
    float s = fb[o];
#pragma unroll 8
    for (int k = 0; k < 80; k++) s += pool[g * 80 + k] * fw[o * 80 + k];
    out[g * 20 + o] = s;
}

// ---------------- host driver ----------------
static void run_gemm(const float* A, int lda, long long as,
                     const float* B, int ldb, long long bs,
                     float* C, int ldc, long long cs,
                     const float* bias, int M, int Nn, int K, int batch) {
    dim3 grid((M + 63) / 64, (Nn + 63) / 64, batch);
    k_gemm<<<grid, 256>>>(A, lda, as, B, ldb, bs, C, ldc, cs, bias, M, Nn, K);
}

extern "C" void kernel_launch(void* const* d_in, const int* in_sizes, int n_in,
                              void* d_out, int out_size) {
    (void)in_sizes; (void)n_in; (void)out_size;
    const int*   x   = (const int*)d_in[0];
    const int*   ei  = (const int*)d_in[1];
    const int*   bat = (const int*)d_in[2];
    const float* emb = (const float*)d_in[3];
    const float *pw[2], *pb[2], *ow[2], *ob[2], *lw[2], *lb[2], *bg[2], *bb[2];
    for (int l = 0; l < 2; l++) {
        int b = 4 + l * 8;
        pw[l] = (const float*)d_in[b + 0];
        pb[l] = (const float*)d_in[b + 1];
        ow[l] = (const float*)d_in[b + 2];
        ob[l] = (const float*)d_in[b + 3];
        lw[l] = (const float*)d_in[b + 4];
        lb[l] = (const float*)d_in[b + 5];
        bg[l] = (const float*)d_in[b + 6];
        bb[l] = (const float*)d_in[b + 7];
    }
    const float* fcw = (const float*)d_in[20];
    const float* fcb = (const float*)d_in[21];
    float* out = (float*)d_out;

    float *h, *hij, *agg, *t48, *tph, *comb, *y, *W1, *W2, *amp, *inva, *pool;
    double *bsum, *bsq;
    int *deg, *off, *cur, *ssrc;
    cudaGetSymbolAddress((void**)&h,    g_h);
    cudaGetSymbolAddress((void**)&hij,  g_hij);
    cudaGetSymbolAddress((void**)&agg,  g_agg);
    cudaGetSymbolAddress((void**)&t48,  g_t48);
    cudaGetSymbolAddress((void**)&tph,  g_tph);
    cudaGetSymbolAddress((void**)&comb, g_comb);
    cudaGetSymbolAddress((void**)&y,    g_y);
    cudaGetSymbolAddress((void**)&W1,   g_W1);
    cudaGetSymbolAddress((void**)&W2,   g_W2);
    cudaGetSymbolAddress((void**)&amp,  g_amp);
    cudaGetSymbolAddress((void**)&inva, g_inv);
    cudaGetSymbolAddress((void**)&pool, g_pool);
    cudaGetSymbolAddress((void**)&bsum, g_bsum);
    cudaGetSymbolAddress((void**)&bsq,  g_bsq);
    cudaGetSymbolAddress((void**)&deg,  g_deg);
    cudaGetSymbolAddress((void**)&off,  g_off);
    cudaGetSymbolAddress((void**)&cur,  g_cur);
    cudaGetSymbolAddress((void**)&ssrc, g_ssrc);

    // embedding + CSR build
    k_embed<<<(kN * 40 + 255) / 256, 256>>>(x, emb, h);
    k_zero_int<<<(kN + 255) / 256, 256>>>(deg, kN);
    k_count<<<(kE + 255) / 256, 256>>>(ei, deg);
    k_scan<<<1, 1024>>>(deg, off, cur);
    k_scatter<<<(kE + 255) / 256, 256>>>(ei, off, cur, ssrc);

    for (int l = 0; l < 2; l++) {
        k_repack1<<<(800 * 80 + 255) / 256, 256>>>(pw[l], W1);
        k_repack2<<<(kT * 48 * 320 + 255) / 256, 256>>>(ow[l], W2);
        // hi|hj = h @ W1^T   [N,800]
        run_gemm(h, 80, 0, W1, 80, 0, hij, 800, 0, nullptr, kN, 800, 80, 1);
        // per-node aggregation -> agg [N,1600], amp, inv
        k_aggregate<<<kN, 128>>>(hij, pb[l], off, ssrc, agg, amp, inva);
        // batched (per tower) agg contraction -> t48 [N, 5, 48]
        run_gemm(agg, 1600, 320, W2, 320, 48 * 320, t48, 240, 48, nullptr, kN, 48, 320, kT);
        // h-part of post MLP (post_w rows are (t,g)-major, k offset 0)
        run_gemm(h, 80, 0, ow[l], 1040, 0, tph, 80, 0, nullptr, kN, 80, 80, 1);
        // combine + post bias
        k_combine<<<(kN * 80 + 255) / 256, 256>>>(tph, t48, amp, inva, ob[l], comb);
        // conv's final Linear(80,80)
        run_gemm(comb, 80, 0, lw[l], 80, 0, y, 80, 0, lb[l], kN, 80, 80, 1);
        // batchnorm (training mode) + relu -> h
        k_zero_bn<<<1, 96>>>(bsum, bsq);
        k_bnstats<<<48, 256>>>(y, bsum, bsq);
        k_bnapply<<<(kN * 80 + 255) / 256, 256>>>(y, bsum, bsq, bg[l], bb[l], h);
    }

    // global max pool per graph + final FC
    k_zero_float<<<(kNG * 80 + 255) / 256, 256>>>(pool, kNG * 80);
    k_pool<<<(kN * 80 + 255) / 256, 256>>>(h, bat, pool);
    k_fc<<<1, 320>>>(pool, fcw, fcb, out);
}